// round 9
// baseline (speedup 1.0000x reference)
#include <cuda_runtime.h>
#include <cuda_fp16.h>
#include <math_constants.h>
#include <cstdint>

// Problem constants
#define B_   16
#define T_   128
#define N_   50
#define D_   512
#define H_   8
#define DH   64
#define TOK  (B_ * T_ * N_)      // 102400 tokens
#define K3   (3 * D_)            // 1536

// ---------------------------------------------------------------------------
// Scratch (device globals: allocation-free per harness rules)
// ---------------------------------------------------------------------------
__device__ __half g_Act[(size_t)TOK * 1024];   // region0: attn out; region1: FFN mid
__device__ __half g_q[(size_t)TOK * D_];
__device__ __half g_k[(size_t)TOK * D_];
__device__ __half g_v[(size_t)TOK * D_];
// Transposed fp16 weights: [Wq;Wk;Wv] stacked (1536 rows x K=1536), then W1, W2.
#define WOFF1 2359296
#define WOFF2 2621440
__device__ __half g_Wh[2883584];

// ---------------------------------------------------------------------------
// helpers
// ---------------------------------------------------------------------------
__device__ __forceinline__ uint32_t smem_u32(const void* p) {
    uint32_t a;
    asm("{ .reg .u64 t; cvta.to.shared.u64 t, %1; cvt.u32.u64 %0, t; }"
        : "=r"(a) : "l"(p));
    return a;
}

#define LDSM_X4(r0, r1, r2, r3, addr)                                         \
    asm volatile("ldmatrix.sync.aligned.m8n8.x4.shared.b16 {%0,%1,%2,%3}, [%4];" \
                 : "=r"(r0), "=r"(r1), "=r"(r2), "=r"(r3) : "r"(addr))

#define LDSM_X4_T(r0, r1, r2, r3, addr)                                       \
    asm volatile("ldmatrix.sync.aligned.m8n8.x4.trans.shared.b16 {%0,%1,%2,%3}, [%4];" \
                 : "=r"(r0), "=r"(r1), "=r"(r2), "=r"(r3) : "r"(addr))

#define MMA16816(d, a, b)                                                     \
    asm volatile("mma.sync.aligned.m16n8k16.row.col.f32.f16.f16.f32 "         \
                 "{%0,%1,%2,%3}, {%4,%5,%6,%7}, {%8,%9}, {%0,%1,%2,%3};"      \
                 : "+f"((d)[0]), "+f"((d)[1]), "+f"((d)[2]), "+f"((d)[3])     \
                 : "r"((a)[0]), "r"((a)[1]), "r"((a)[2]), "r"((a)[3]),        \
                   "r"((b)[0]), "r"((b)[1]))

#define CP16(dst, src)                                                        \
    asm volatile("cp.async.cg.shared.global [%0], [%1], 16;"                  \
                 :: "r"(dst), "l"(src))

__device__ __forceinline__ uint32_t packh2(float x, float y) {
    __half2 h = __floats2half2_rn(x, y);
    return *(uint32_t*)&h;
}

// ---------------------------------------------------------------------------
// All weight transposes in one launch.
// ---------------------------------------------------------------------------
__global__ void wtrans_all_kernel(const float* __restrict__ Wq,
                                  const float* __restrict__ Wk,
                                  const float* __restrict__ Wv,
                                  const float* __restrict__ W1,
                                  const float* __restrict__ W2) {
    int idx = blockIdx.x * 256 + threadIdx.x;
    const float* src;
    float v;
    if (idx < WOFF1) {
        int sel = idx / 786432, i = idx - sel * 786432;
        int n = i / K3, k = i - n * K3;
        src = (sel == 0) ? Wq : (sel == 1) ? Wk : Wv;
        v = src[(size_t)k * 512 + n];
    } else {
        int j = idx - WOFF1;
        int sel = j >> 18, i = j & 262143;
        int n = i >> 9, k = i & 511;
        src = sel ? W2 : W1;
        v = src[(size_t)k * 512 + n];
    }
    g_Wh[idx] = __float2half_rn(v);
}

// ---------------------------------------------------------------------------
// Fused QKV GEMM: reads A directly from fp32 X / TLE (concat implied),
// converts to fp16 in smem, HMMA mainloop. CTA 128x256, 8 warps, BK=64.
// Smem layout: B stages (3 x 36864) | A32 stages (2 x 36864) | A16 (2 x 18432)
// ---------------------------------------------------------------------------
#define QF_B    0
#define QF_A32  110592
#define QF_A16  184320
#define QF_SMEM 221184

__global__ void __launch_bounds__(256)
qkv_gemm_fused(const float* __restrict__ X, const float* __restrict__ TLE,
               const __half* __restrict__ Bw,
               const float* __restrict__ bq, const float* __restrict__ bk,
               const float* __restrict__ bv,
               __half* __restrict__ Cq, __half* __restrict__ Ck,
               __half* __restrict__ Cv) {
    extern __shared__ char sm[];
    uint32_t sbase = smem_u32(sm);
    const int KD = K3;

    int tid = threadIdx.x, wid = tid >> 5, lane = tid & 31;
    int bx = blockIdx.x;
    int warpM = (wid >> 2) * 64;
    int warpN = (wid & 3) * 64;

    const float*  Xb   = X   + (size_t)blockIdx.y * 128 * 512;
    const float*  Tb   = TLE + (size_t)blockIdx.y * 128 * 1024;
    const __half* srcB = Bw  + (size_t)bx * 256 * KD;

    float acc[4][8][4];
#pragma unroll
    for (int i = 0; i < 4; i++)
#pragma unroll
        for (int j = 0; j < 8; j++)
#pragma unroll
            for (int e = 0; e < 4; e++) acc[i][j][e] = 0.f;

    // issue chunk c: fp32 A (from X or TLE) + fp16 B weights
    auto issue = [&](int c) {
        uint32_t bst = sbase + QF_B   + (uint32_t)((c % 3) * 36864);
        uint32_t a32 = sbase + QF_A32 + (uint32_t)((c & 1) * 36864);
        const float* arow;
        int astr;
        if (c < 8) { arow = Xb + c * 64;       astr = 512;  }
        else       { arow = Tb + c * 64 - 512; astr = 1024; }
        int k0 = c * 64;
#pragma unroll
        for (int j = 0; j < 8; j++) {          // A32: 128 rows x 16 segs
            int idx = tid + j * 256;
            int r = idx >> 4, s = idx & 15;
            const float* g = arow + (size_t)r * astr + s * 4;
            CP16(a32 + (uint32_t)(r * 288 + s * 16), g);
        }
#pragma unroll
        for (int j = 0; j < 8; j++) {          // B: 256 rows x 8 segs
            int idx = tid + j * 256;
            int r = idx >> 3, s = idx & 7;
            const __half* g = srcB + (size_t)r * KD + k0 + s * 8;
            CP16(bst + (uint32_t)(r * 144 + s * 16), g);
        }
        asm volatile("cp.async.commit_group;");
    };

    // convert chunk c's fp32 A staging -> fp16 ldmatrix tile
    auto cvtA = [&](int c) {
        char* a32 = sm + QF_A32 + (c & 1) * 36864;
        char* a16 = sm + QF_A16 + (c & 1) * 18432;
#pragma unroll
        for (int j = 0; j < 4; j++) {          // 128 rows x 8 half-segs
            int idx = tid + j * 256;
            int r = idx >> 3, s = idx & 7;
            const float4* p = (const float4*)(a32 + r * 288 + s * 32);
            float4 f0 = p[0], f1 = p[1];
            uint32_t h[4];
            h[0] = packh2(f0.x, f0.y); h[1] = packh2(f0.z, f0.w);
            h[2] = packh2(f1.x, f1.y); h[3] = packh2(f1.z, f1.w);
            *(uint4*)(a16 + r * 144 + s * 16) = *(uint4*)h;
        }
    };

    uint32_t aoff = (uint32_t)((warpM + (lane & 15)) * 144 + (lane >> 4) * 16);
    uint32_t boff = (uint32_t)((warpN + ((lane >> 4) << 3) + (lane & 7)) * 144 +
                               ((lane >> 3) & 1) * 16);

    auto ldfrag = [&](uint32_t a16b, uint32_t bb, int kk,
                      uint32_t (*Af)[4], uint32_t (*Bf)[2]) {
#pragma unroll
        for (int mt = 0; mt < 4; mt++) {
            uint32_t ad = a16b + aoff + mt * (16 * 144) + kk * 32;
            LDSM_X4(Af[mt][0], Af[mt][1], Af[mt][2], Af[mt][3], ad);
        }
#pragma unroll
        for (int np = 0; np < 4; np++) {
            uint32_t bd = bb + boff + np * (16 * 144) + kk * 32;
            LDSM_X4(Bf[2*np][0], Bf[2*np][1], Bf[2*np+1][0], Bf[2*np+1][1], bd);
        }
    };

    uint32_t ah[2][4][4], bh8[2][8][2];

    // prologue
    issue(0);
    issue(1);
    asm volatile("cp.async.wait_group 1;");
    __syncthreads();
    cvtA(0);
    asm volatile("cp.async.wait_group 0;");

    const int nch = KD / 64;   // 24
    for (int c = 0; c < nch; c++) {
        __syncthreads();
        if (c + 2 < nch) issue(c + 2);
        if (c + 1 < nch) cvtA(c + 1);

        uint32_t a16b = sbase + QF_A16 + (uint32_t)((c & 1) * 18432);
        uint32_t bb   = sbase + QF_B   + (uint32_t)((c % 3) * 36864);
        ldfrag(a16b, bb, 0, ah[0], bh8[0]);
#pragma unroll
        for (int kk = 0; kk < 4; kk++) {
            int cur = kk & 1;
            if (kk < 3) ldfrag(a16b, bb, kk + 1, ah[cur ^ 1], bh8[cur ^ 1]);
#pragma unroll
            for (int mt = 0; mt < 4; mt++)
#pragma unroll
                for (int nt = 0; nt < 8; nt++)
                    MMA16816(acc[mt][nt], ah[cur][mt], bh8[cur][nt]);
        }
        asm volatile("cp.async.wait_group 0;");
    }

    // Epilogue: bias + relu -> fp16, output stride 512
    int reg = bx >> 1;
    const float* bias = (reg == 0) ? bq : (reg == 1) ? bk : bv;
    __half* Cp        = (reg == 0) ? Cq : (reg == 1) ? Ck : Cv;
    int row0 = blockIdx.y * 128 + warpM + (lane >> 2);
    int col0 = (bx & 1) * 256 + warpN + (lane & 3) * 2;
#pragma unroll
    for (int mt = 0; mt < 4; mt++) {
#pragma unroll
        for (int nt = 0; nt < 8; nt++) {
            int r = row0 + mt * 16;
            int cc = col0 + nt * 8;
            float b0 = bias[cc], b1 = bias[cc + 1];
            float x0 = fmaxf(acc[mt][nt][0] + b0, 0.f);
            float y0 = fmaxf(acc[mt][nt][1] + b1, 0.f);
            float x1 = fmaxf(acc[mt][nt][2] + b0, 0.f);
            float y1 = fmaxf(acc[mt][nt][3] + b1, 0.f);
            *(__half2*)(Cp + (size_t)r * 512 + cc)       = __floats2half2_rn(x0, y0);
            *(__half2*)(Cp + (size_t)(r + 8) * 512 + cc) = __floats2half2_rn(x1, y1);
        }
    }
}

// ---------------------------------------------------------------------------
// FFN GEMM (fp16 A via cp.async, 3-stage) — unchanged from R8.
// ---------------------------------------------------------------------------
#define PSTR     72
#define ARR_A    (128 * PSTR * 2)
#define ARR_Bt   (256 * PSTR * 2)
#define STAGE_B  (ARR_A + ARR_Bt)
#define NSTAGE   3
#define SMEM_B   (NSTAGE * STAGE_B)

template<int HOUT>
__global__ void __launch_bounds__(256)
mma_gemm(const __half* __restrict__ A, const __half* __restrict__ Bh,
         const float* __restrict__ bias, void* C) {
    const int KDIM = 512;
    extern __shared__ char sm[];
    uint32_t sbase = smem_u32(sm);

    int tid = threadIdx.x, wid = tid >> 5, lane = tid & 31;
    int bx = blockIdx.x;
    int warpM = (wid >> 2) * 64;
    int warpN = (wid & 3) * 64;

    const __half* srcA = A  + (size_t)blockIdx.y * 128 * KDIM;
    const __half* srcB = Bh + (size_t)bx * 256 * KDIM;

    float acc[4][8][4];
#pragma unroll
    for (int i = 0; i < 4; i++)
#pragma unroll
        for (int j = 0; j < 8; j++)
#pragma unroll
            for (int e = 0; e < 4; e++) acc[i][j][e] = 0.f;

    auto issue = [&](int c) {
        uint32_t stb = sbase + (uint32_t)((c % NSTAGE) * STAGE_B);
        int k0 = c * 64;
#pragma unroll
        for (int j = 0; j < 12; j++) {
            int idx = tid + j * 256;
            const __half* g;
            uint32_t d;
            if (idx < 1024) {
                int r = idx >> 3, s = idx & 7;
                g = srcA + (size_t)r * KDIM + k0 + s * 8;
                d = stb + (uint32_t)(r * (PSTR * 2) + s * 16);
            } else {
                int r = (idx - 1024) >> 3, s = idx & 7;
                g = srcB + (size_t)r * KDIM + k0 + s * 8;
                d = stb + (uint32_t)(ARR_A + r * (PSTR * 2) + s * 16);
            }
            CP16(d, g);
        }
        asm volatile("cp.async.commit_group;");
    };

    uint32_t aoff = (uint32_t)((warpM + (lane & 15)) * (PSTR * 2) + (lane >> 4) * 16);
    uint32_t boff = (uint32_t)(ARR_A +
                    (warpN + ((lane >> 4) << 3) + (lane & 7)) * (PSTR * 2) +
                    ((lane >> 3) & 1) * 16);

    auto ldfrag = [&](uint32_t stage, int kk, uint32_t (*Af)[4], uint32_t (*Bf)[2]) {
#pragma unroll
        for (int mt = 0; mt < 4; mt++) {
            uint32_t ad = stage + aoff + mt * (16 * PSTR * 2) + kk * 32;
            LDSM_X4(Af[mt][0], Af[mt][1], Af[mt][2], Af[mt][3], ad);
        }
#pragma unroll
        for (int np = 0; np < 4; np++) {
            uint32_t bd = stage + boff + np * (16 * PSTR * 2) + kk * 32;
            LDSM_X4(Bf[2*np][0], Bf[2*np][1], Bf[2*np+1][0], Bf[2*np+1][1], bd);
        }
    };

    uint32_t ah[2][4][4], bh8[2][8][2];

    const int nch = KDIM / 64;
    issue(0);
    issue(1);
    for (int c = 0; c < nch; c++) {
        if (c + 1 < nch) asm volatile("cp.async.wait_group 1;");
        else             asm volatile("cp.async.wait_group 0;");
        __syncthreads();
        if (c + 2 < nch) issue(c + 2);

        uint32_t stage = sbase + (uint32_t)((c % NSTAGE) * STAGE_B);
        ldfrag(stage, 0, ah[0], bh8[0]);
#pragma unroll
        for (int kk = 0; kk < 4; kk++) {
            int cur = kk & 1;
            if (kk < 3) ldfrag(stage, kk + 1, ah[cur ^ 1], bh8[cur ^ 1]);
#pragma unroll
            for (int mt = 0; mt < 4; mt++)
#pragma unroll
                for (int nt = 0; nt < 8; nt++)
                    MMA16816(acc[mt][nt], ah[cur][mt], bh8[cur][nt]);
        }
    }

    int row0 = blockIdx.y * 128 + warpM + (lane >> 2);
    int col0 = (bx & 1) * 256 + warpN + (lane & 3) * 2;
#pragma unroll
    for (int mt = 0; mt < 4; mt++) {
#pragma unroll
        for (int nt = 0; nt < 8; nt++) {
            int r = row0 + mt * 16;
            int cc = col0 + nt * 8;
            float b0 = bias[cc], b1 = bias[cc + 1];
            float2 d0, d1;
            d0.x = acc[mt][nt][0] + b0; d0.y = acc[mt][nt][1] + b1;
            d1.x = acc[mt][nt][2] + b0; d1.y = acc[mt][nt][3] + b1;
            if (HOUT) {
                d0.x = fmaxf(d0.x, 0.f); d0.y = fmaxf(d0.y, 0.f);
                d1.x = fmaxf(d1.x, 0.f); d1.y = fmaxf(d1.y, 0.f);
                __half* Ch = (__half*)C;
                *(__half2*)(Ch + (size_t)r * 512 + cc)       = __floats2half2_rn(d0.x, d0.y);
                *(__half2*)(Ch + (size_t)(r + 8) * 512 + cc) = __floats2half2_rn(d1.x, d1.y);
            } else {
                float* Cf = (float*)C;
                *(float2*)(Cf + (size_t)r * 512 + cc)       = d0;
                *(float2*)(Cf + (size_t)(r + 8) * 512 + cc) = d1;
            }
        }
    }
}

// ---------------------------------------------------------------------------
// Tensor-core causal attention with causal tile-skipping.
// One CTA per (b, n, head), 8 warps; warp wq owns q-rows [wq*16, wq*16+16).
// Key tiles nt2 > min(wq, (L-1)>>4) are entirely masked -> skipped.
// ---------------------------------------------------------------------------
#define ATT_ROWB 144
#define ATT_ARR  (128 * ATT_ROWB)
#define ATT_SMEM (3 * ATT_ARR)

__global__ void __launch_bounds__(256)
attn_tc_kernel(const int* __restrict__ kpm,
               const __half* __restrict__ Q, const __half* __restrict__ Kp,
               const __half* __restrict__ V, __half* __restrict__ outp) {
    extern __shared__ char sm[];
    uint32_t sb = smem_u32(sm);

    int bid = blockIdx.x;
    int h = bid & 7;
    int n = (bid >> 3) % N_;
    int b = bid / (H_ * N_);
    int tid = threadIdx.x, wq = tid >> 5, lane = tid & 31;
    int L = kpm[b];
    int RN = ((L + 15) >> 4) << 4;          // K/V rows actually needed
    if (RN > 128) RN = 128;

    size_t base = ((size_t)(b * T_) * N_ + n) * D_ + h * DH;
    const size_t rstride = (size_t)N_ * D_;

    // stage Q (all rows), K/V (rows < RN)
#pragma unroll
    for (int j = 0; j < 12; j++) {
        int idx = tid + j * 256;
        int arr = idx >> 10, rem = idx & 1023;
        int r = rem >> 3, s = rem & 7;
        if (arr == 0 || r < RN) {
            const __half* src = ((arr == 0) ? Q : (arr == 1) ? Kp : V)
                                + base + (size_t)r * rstride + s * 8;
            *(uint4*)(sm + arr * ATT_ARR + r * ATT_ROWB + s * 16) = *(const uint4*)src;
        }
    }
    __syncthreads();

    int kmax = min(wq, (L - 1) >> 4);       // inclusive 16-key tile bound

    // Q fragments
    uint32_t qa[4][4];
#pragma unroll
    for (int kt = 0; kt < 4; kt++) {
        uint32_t ad = sb + (wq * 16 + (lane & 15)) * ATT_ROWB
                         + (kt * 16 + (lane >> 4) * 8) * 2;
        LDSM_X4(qa[kt][0], qa[kt][1], qa[kt][2], qa[kt][3], ad);
    }

    // S = Q K^T over needed tiles only
    float sa[16][4];
#pragma unroll
    for (int nt2 = 0; nt2 < 8; nt2++) {
        if (nt2 > kmax) continue;
        sa[2*nt2][0] = sa[2*nt2][1] = sa[2*nt2][2] = sa[2*nt2][3] = 0.f;
        sa[2*nt2+1][0] = sa[2*nt2+1][1] = sa[2*nt2+1][2] = sa[2*nt2+1][3] = 0.f;
#pragma unroll
        for (int kt = 0; kt < 4; kt++) {
            uint32_t bk0[2], bk1[2];
            uint32_t bd = sb + ATT_ARR
                        + (nt2 * 16 + ((lane >> 4) << 3) + (lane & 7)) * ATT_ROWB
                        + (kt * 16 + ((lane >> 3) & 1) * 8) * 2;
            LDSM_X4(bk0[0], bk0[1], bk1[0], bk1[1], bd);
            MMA16816(sa[2 * nt2],     qa[kt], bk0);
            MMA16816(sa[2 * nt2 + 1], qa[kt], bk1);
        }
    }

    // mask + softmax
    const float NEGINF = -CUDART_INF_F;
    int r0 = wq * 16 + (lane >> 2);
    int r1 = r0 + 8;
    int c2 = (lane & 3) * 2;
    float m0 = NEGINF, m1 = NEGINF;
#pragma unroll
    for (int nt = 0; nt < 16; nt++) {
        if ((nt >> 1) > kmax) continue;
        int c0 = nt * 8 + c2;
#pragma unroll
        for (int e = 0; e < 4; e++) {
            int col = c0 + (e & 1);
            int row = (e < 2) ? r0 : r1;
            float s = sa[nt][e] * 0.125f;
            if (col > row || col >= L) s = NEGINF;
            sa[nt][e] = s;
            if (e < 2) m0 = fmaxf(m0, s); else m1 = fmaxf(m1, s);
        }
    }
    m0 = fmaxf(m0, __shfl_xor_sync(0xffffffffu, m0, 1));
    m0 = fmaxf(m0, __shfl_xor_sync(0xffffffffu, m0, 2));
    m1 = fmaxf(m1, __shfl_xor_sync(0xffffffffu, m1, 1));
    m1 = fmaxf(m1, __shfl_xor_sync(0xffffffffu, m1, 2));

    float l0 = 0.f, l1 = 0.f;
#pragma unroll
    for (int nt = 0; nt < 16; nt++) {
        if ((nt >> 1) > kmax) continue;
#pragma unroll
        for (int e = 0; e < 4; e++) {
            float p = __expf(sa[nt][e] - ((e < 2) ? m0 : m1));
            sa[nt][e] = p;
            if (e < 2) l0 += p; else l1 += p;
        }
    }
    l0 += __shfl_xor_sync(0xffffffffu, l0, 1);
    l0 += __shfl_xor_sync(0xffffffffu, l0, 2);
    l1 += __shfl_xor_sync(0xffffffffu, l1, 1);
    l1 += __shfl_xor_sync(0xffffffffu, l1, 2);

    // O = P V over needed key tiles only
    float oa[8][4];
#pragma unroll
    for (int dt = 0; dt < 8; dt++)
#pragma unroll
        for (int e = 0; e < 4; e++) oa[dt][e] = 0.f;

#pragma unroll
    for (int kt = 0; kt < 8; kt++) {
        if (kt > kmax) continue;
        uint32_t pa[4];
        pa[0] = packh2(sa[2 * kt][0],     sa[2 * kt][1]);
        pa[1] = packh2(sa[2 * kt][2],     sa[2 * kt][3]);
        pa[2] = packh2(sa[2 * kt + 1][0], sa[2 * kt + 1][1]);
        pa[3] = packh2(sa[2 * kt + 1][2], sa[2 * kt + 1][3]);
#pragma unroll
        for (int dt2 = 0; dt2 < 4; dt2++) {
            uint32_t bv0[2], bv1[2];
            uint32_t bd = sb + 2 * ATT_ARR
                        + (kt * 16 + ((lane >> 3) & 1) * 8 + (lane & 7)) * ATT_ROWB
                        + (dt2 * 16 + ((lane >> 4) << 3)) * 2;
            LDSM_X4_T(bv0[0], bv0[1], bv1[0], bv1[1], bd);
            MMA16816(oa[2 * dt2],     pa, bv0);
            MMA16816(oa[2 * dt2 + 1], pa, bv1);
        }
    }

    float inv0 = 1.f / l0, inv1 = 1.f / l1;
    __half* op0 = outp + base + (size_t)r0 * rstride;
    __half* op1 = outp + base + (size_t)r1 * rstride;
#pragma unroll
    for (int dt = 0; dt < 8; dt++) {
        int c = dt * 8 + c2;
        *(__half2*)(op0 + c) = __floats2half2_rn(oa[dt][0] * inv0, oa[dt][1] * inv0);
        *(__half2*)(op1 + c) = __floats2half2_rn(oa[dt][2] * inv1, oa[dt][3] * inv1);
    }
}

// ---------------------------------------------------------------------------
extern "C" void kernel_launch(void* const* d_in, const int* in_sizes, int n_in,
                              void* d_out, int out_size) {
    const float* X   = (const float*)d_in[0];
    const float* TLE = (const float*)d_in[1];
    const int*   kpm = (const int*)  d_in[2];
    const float* Wq  = (const float*)d_in[3];
    const float* bq  = (const float*)d_in[4];
    const float* Wk  = (const float*)d_in[5];
    const float* bk  = (const float*)d_in[6];
    const float* Wv  = (const float*)d_in[7];
    const float* bv  = (const float*)d_in[8];
    const float* W1  = (const float*)d_in[9];
    const float* b1  = (const float*)d_in[10];
    const float* W2  = (const float*)d_in[11];
    const float* b2  = (const float*)d_in[12];
    float* out = (float*)d_out;

    __half *pAct, *pWh, *pq, *pk, *pv;
    cudaGetSymbolAddress((void**)&pAct, g_Act);
    cudaGetSymbolAddress((void**)&pWh, g_Wh);
    cudaGetSymbolAddress((void**)&pq, g_q);
    cudaGetSymbolAddress((void**)&pk, g_k);
    cudaGetSymbolAddress((void**)&pv, g_v);

    __half* actR0 = pAct;                       // attn out / W1 input
    __half* actR1 = pAct + (size_t)TOK * D_;    // FFN mid

    cudaFuncSetAttribute((const void*)qkv_gemm_fused,
                         cudaFuncAttributeMaxDynamicSharedMemorySize, QF_SMEM);
    cudaFuncSetAttribute((const void*)mma_gemm<1>,
                         cudaFuncAttributeMaxDynamicSharedMemorySize, SMEM_B);
    cudaFuncSetAttribute((const void*)mma_gemm<0>,
                         cudaFuncAttributeMaxDynamicSharedMemorySize, SMEM_B);
    cudaFuncSetAttribute((const void*)attn_tc_kernel,
                         cudaFuncAttributeMaxDynamicSharedMemorySize, ATT_SMEM);

    // 1. transpose all weights -> fp16 (single launch)
    wtrans_all_kernel<<<2883584 / 256, 256>>>(Wq, Wk, Wv, W1, W2);

    // 2. fused conv_H + QKV projection
    qkv_gemm_fused<<<dim3(6, TOK / 128), 256, QF_SMEM>>>(
        X, TLE, pWh, bq, bk, bv, pq, pk, pv);

    // 3. tensor-core causal attention -> fp16 region0
    attn_tc_kernel<<<B_ * N_ * H_, 256, ATT_SMEM>>>(kpm, pq, pk, pv, actR0);

    // 4. FFN
    mma_gemm<1><<<dim3(2, TOK / 128), 256, SMEM_B>>>(actR0, pWh + WOFF1, b1, actR1);
    mma_gemm<0><<<dim3(2, TOK / 128), 256, SMEM_B>>>(actR1, pWh + WOFF2, b2, out);
}

// round 10
// speedup vs baseline: 1.0017x; 1.0017x over previous
#include <cuda_runtime.h>
#include <cuda_fp16.h>
#include <math_constants.h>
#include <cstdint>

// Problem constants
#define B_   16
#define T_   128
#define N_   50
#define D_   512
#define H_   8
#define DH   64
#define TOK  (B_ * T_ * N_)      // 102400 tokens
#define K3   (3 * D_)            // 1536

// ---------------------------------------------------------------------------
// Scratch (device globals: allocation-free per harness rules)
// ---------------------------------------------------------------------------
__device__ __half g_Act[(size_t)TOK * 1024];   // region0: attn out; region1: FFN mid
__device__ __half g_q[(size_t)TOK * D_];
__device__ __half g_k[(size_t)TOK * D_];
__device__ __half g_v[(size_t)TOK * D_];
// Transposed fp16 weights: [Wq;Wk;Wv] stacked (1536 rows x K=1536), then W1, W2.
#define WOFF1 2359296
#define WOFF2 2621440
__device__ __half g_Wh[2883584];

// ---------------------------------------------------------------------------
// helpers
// ---------------------------------------------------------------------------
__device__ __forceinline__ uint32_t smem_u32(const void* p) {
    uint32_t a;
    asm("{ .reg .u64 t; cvta.to.shared.u64 t, %1; cvt.u32.u64 %0, t; }"
        : "=r"(a) : "l"(p));
    return a;
}

#define LDSM_X4(r0, r1, r2, r3, addr)                                         \
    asm volatile("ldmatrix.sync.aligned.m8n8.x4.shared.b16 {%0,%1,%2,%3}, [%4];" \
                 : "=r"(r0), "=r"(r1), "=r"(r2), "=r"(r3) : "r"(addr))

#define LDSM_X4_T(r0, r1, r2, r3, addr)                                       \
    asm volatile("ldmatrix.sync.aligned.m8n8.x4.trans.shared.b16 {%0,%1,%2,%3}, [%4];" \
                 : "=r"(r0), "=r"(r1), "=r"(r2), "=r"(r3) : "r"(addr))

#define MMA16816(d, a, b)                                                     \
    asm volatile("mma.sync.aligned.m16n8k16.row.col.f32.f16.f16.f32 "         \
                 "{%0,%1,%2,%3}, {%4,%5,%6,%7}, {%8,%9}, {%0,%1,%2,%3};"      \
                 : "+f"((d)[0]), "+f"((d)[1]), "+f"((d)[2]), "+f"((d)[3])     \
                 : "r"((a)[0]), "r"((a)[1]), "r"((a)[2]), "r"((a)[3]),        \
                   "r"((b)[0]), "r"((b)[1]))

#define CP16(dst, src)                                                        \
    asm volatile("cp.async.cg.shared.global [%0], [%1], 16;"                  \
                 :: "r"(dst), "l"(src))

__device__ __forceinline__ uint32_t packh2(float x, float y) {
    __half2 h = __floats2half2_rn(x, y);
    return *(uint32_t*)&h;
}

// ---------------------------------------------------------------------------
// All weight transposes in one launch.
// ---------------------------------------------------------------------------
__global__ void wtrans_all_kernel(const float* __restrict__ Wq,
                                  const float* __restrict__ Wk,
                                  const float* __restrict__ Wv,
                                  const float* __restrict__ W1,
                                  const float* __restrict__ W2) {
    int idx = blockIdx.x * 256 + threadIdx.x;
    const float* src;
    float v;
    if (idx < WOFF1) {
        int sel = idx / 786432, i = idx - sel * 786432;
        int n = i / K3, k = i - n * K3;
        src = (sel == 0) ? Wq : (sel == 1) ? Wk : Wv;
        v = src[(size_t)k * 512 + n];
    } else {
        int j = idx - WOFF1;
        int sel = j >> 18, i = j & 262143;
        int n = i >> 9, k = i & 511;
        src = sel ? W2 : W1;
        v = src[(size_t)k * 512 + n];
    }
    g_Wh[idx] = __float2half_rn(v);
}

// ---------------------------------------------------------------------------
// Fused QKV GEMM: A read as fp32 from X / TLE (concat implied), converted
// to fp16 in smem one chunk ahead. CTA 128x256, 8 warps, BK=64.
// Pipeline (fixed R9 bug): wait drains ONLY the next chunk's group;
// issue(c+2) is committed AFTER the wait so its flight covers compute(c).
// Smem: B stages (3 x 36864) | A32 (2 x 36864) | A16 (2 x 18432)
// ---------------------------------------------------------------------------
#define QF_B    0
#define QF_A32  110592
#define QF_A16  184320
#define QF_SMEM 221184

__global__ void __launch_bounds__(256)
qkv_gemm_fused(const float* __restrict__ X, const float* __restrict__ TLE,
               const __half* __restrict__ Bw,
               const float* __restrict__ bq, const float* __restrict__ bk,
               const float* __restrict__ bv,
               __half* __restrict__ Cq, __half* __restrict__ Ck,
               __half* __restrict__ Cv) {
    extern __shared__ char sm[];
    uint32_t sbase = smem_u32(sm);
    const int KD = K3;

    int tid = threadIdx.x, wid = tid >> 5, lane = tid & 31;
    int bx = blockIdx.x;
    int warpM = (wid >> 2) * 64;
    int warpN = (wid & 3) * 64;

    const float*  Xb   = X   + (size_t)blockIdx.y * 128 * 512;
    const float*  Tb   = TLE + (size_t)blockIdx.y * 128 * 1024;
    const __half* srcB = Bw  + (size_t)bx * 256 * KD;

    float acc[4][8][4];
#pragma unroll
    for (int i = 0; i < 4; i++)
#pragma unroll
        for (int j = 0; j < 8; j++)
#pragma unroll
            for (int e = 0; e < 4; e++) acc[i][j][e] = 0.f;

    // issue chunk c: fp32 A (from X or TLE) + fp16 B weights, one commit group
    auto issue = [&](int c) {
        uint32_t bst = sbase + QF_B   + (uint32_t)((c % 3) * 36864);
        uint32_t a32 = sbase + QF_A32 + (uint32_t)((c & 1) * 36864);
        const float* arow;
        int astr;
        if (c < 8) { arow = Xb + c * 64;       astr = 512;  }
        else       { arow = Tb + c * 64 - 512; astr = 1024; }
        int k0 = c * 64;
#pragma unroll
        for (int j = 0; j < 8; j++) {          // A32: 128 rows x 16 segs
            int idx = tid + j * 256;
            int r = idx >> 4, s = idx & 15;
            const float* g = arow + (size_t)r * astr + s * 4;
            CP16(a32 + (uint32_t)(r * 288 + s * 16), g);
        }
#pragma unroll
        for (int j = 0; j < 8; j++) {          // B: 256 rows x 8 segs
            int idx = tid + j * 256;
            int r = idx >> 3, s = idx & 7;
            const __half* g = srcB + (size_t)r * KD + k0 + s * 8;
            CP16(bst + (uint32_t)(r * 144 + s * 16), g);
        }
        asm volatile("cp.async.commit_group;");
    };

    // convert chunk c's fp32 A staging -> fp16 ldmatrix tile
    auto cvtA = [&](int c) {
        char* a32 = sm + QF_A32 + (c & 1) * 36864;
        char* a16 = sm + QF_A16 + (c & 1) * 18432;
#pragma unroll
        for (int j = 0; j < 4; j++) {          // 128 rows x 8 half-segs
            int idx = tid + j * 256;
            int r = idx >> 3, s = idx & 7;
            const float4* p = (const float4*)(a32 + r * 288 + s * 32);
            float4 f0 = p[0], f1 = p[1];
            uint32_t h[4];
            h[0] = packh2(f0.x, f0.y); h[1] = packh2(f0.z, f0.w);
            h[2] = packh2(f1.x, f1.y); h[3] = packh2(f1.z, f1.w);
            *(uint4*)(a16 + r * 144 + s * 16) = *(uint4*)h;
        }
    };

    uint32_t aoff = (uint32_t)((warpM + (lane & 15)) * 144 + (lane >> 4) * 16);
    uint32_t boff = (uint32_t)((warpN + ((lane >> 4) << 3) + (lane & 7)) * 144 +
                               ((lane >> 3) & 1) * 16);

    auto ldfrag = [&](uint32_t a16b, uint32_t bb, int kk,
                      uint32_t (*Af)[4], uint32_t (*Bf)[2]) {
#pragma unroll
        for (int mt = 0; mt < 4; mt++) {
            uint32_t ad = a16b + aoff + mt * (16 * 144) + kk * 32;
            LDSM_X4(Af[mt][0], Af[mt][1], Af[mt][2], Af[mt][3], ad);
        }
#pragma unroll
        for (int np = 0; np < 4; np++) {
            uint32_t bd = bb + boff + np * (16 * 144) + kk * 32;
            LDSM_X4(Bf[2*np][0], Bf[2*np][1], Bf[2*np+1][0], Bf[2*np+1][1], bd);
        }
    };

    uint32_t ah[2][4][4], bh8[2][8][2];

    // prologue: group 0 arrives, convert chunk 0
    issue(0);
    issue(1);
    asm volatile("cp.async.wait_group 1;");    // group 0 done ({0,1} pending)
    __syncthreads();                           // cross-thread visibility
    cvtA(0);

    const int nch = KD / 64;   // 24
    for (int c = 0; c < nch; c++) {
        // pending here is exactly {c+1} (if any): drain it only.
        asm volatile("cp.async.wait_group 0;");
        __syncthreads();       // group c+1 visible; cvtA(c) visible; smem reuse safe
        if (c + 2 < nch) issue(c + 2);         // flies over compute(c)
        if (c + 1 < nch) cvtA(c + 1);

        uint32_t a16b = sbase + QF_A16 + (uint32_t)((c & 1) * 18432);
        uint32_t bb   = sbase + QF_B   + (uint32_t)((c % 3) * 36864);
        ldfrag(a16b, bb, 0, ah[0], bh8[0]);
#pragma unroll
        for (int kk = 0; kk < 4; kk++) {
            int cur = kk & 1;
            if (kk < 3) ldfrag(a16b, bb, kk + 1, ah[cur ^ 1], bh8[cur ^ 1]);
#pragma unroll
            for (int mt = 0; mt < 4; mt++)
#pragma unroll
                for (int nt = 0; nt < 8; nt++)
                    MMA16816(acc[mt][nt], ah[cur][mt], bh8[cur][nt]);
        }
    }

    // Epilogue: bias + relu -> fp16, output stride 512
    int reg = bx >> 1;
    const float* bias = (reg == 0) ? bq : (reg == 1) ? bk : bv;
    __half* Cp        = (reg == 0) ? Cq : (reg == 1) ? Ck : Cv;
    int row0 = blockIdx.y * 128 + warpM + (lane >> 2);
    int col0 = (bx & 1) * 256 + warpN + (lane & 3) * 2;
#pragma unroll
    for (int mt = 0; mt < 4; mt++) {
#pragma unroll
        for (int nt = 0; nt < 8; nt++) {
            int r = row0 + mt * 16;
            int cc = col0 + nt * 8;
            float b0 = bias[cc], b1 = bias[cc + 1];
            float x0 = fmaxf(acc[mt][nt][0] + b0, 0.f);
            float y0 = fmaxf(acc[mt][nt][1] + b1, 0.f);
            float x1 = fmaxf(acc[mt][nt][2] + b0, 0.f);
            float y1 = fmaxf(acc[mt][nt][3] + b1, 0.f);
            *(__half2*)(Cp + (size_t)r * 512 + cc)       = __floats2half2_rn(x0, y0);
            *(__half2*)(Cp + (size_t)(r + 8) * 512 + cc) = __floats2half2_rn(x1, y1);
        }
    }
}

// ---------------------------------------------------------------------------
// FFN GEMM (fp16 A via cp.async, 3-stage) — unchanged (proven in R8/R9).
// ---------------------------------------------------------------------------
#define PSTR     72
#define ARR_A    (128 * PSTR * 2)
#define ARR_Bt   (256 * PSTR * 2)
#define STAGE_B  (ARR_A + ARR_Bt)
#define NSTAGE   3
#define SMEM_B   (NSTAGE * STAGE_B)

template<int HOUT>
__global__ void __launch_bounds__(256)
mma_gemm(const __half* __restrict__ A, const __half* __restrict__ Bh,
         const float* __restrict__ bias, void* C) {
    const int KDIM = 512;
    extern __shared__ char sm[];
    uint32_t sbase = smem_u32(sm);

    int tid = threadIdx.x, wid = tid >> 5, lane = tid & 31;
    int bx = blockIdx.x;
    int warpM = (wid >> 2) * 64;
    int warpN = (wid & 3) * 64;

    const __half* srcA = A  + (size_t)blockIdx.y * 128 * KDIM;
    const __half* srcB = Bh + (size_t)bx * 256 * KDIM;

    float acc[4][8][4];
#pragma unroll
    for (int i = 0; i < 4; i++)
#pragma unroll
        for (int j = 0; j < 8; j++)
#pragma unroll
            for (int e = 0; e < 4; e++) acc[i][j][e] = 0.f;

    auto issue = [&](int c) {
        uint32_t stb = sbase + (uint32_t)((c % NSTAGE) * STAGE_B);
        int k0 = c * 64;
#pragma unroll
        for (int j = 0; j < 12; j++) {
            int idx = tid + j * 256;
            const __half* g;
            uint32_t d;
            if (idx < 1024) {
                int r = idx >> 3, s = idx & 7;
                g = srcA + (size_t)r * KDIM + k0 + s * 8;
                d = stb + (uint32_t)(r * (PSTR * 2) + s * 16);
            } else {
                int r = (idx - 1024) >> 3, s = idx & 7;
                g = srcB + (size_t)r * KDIM + k0 + s * 8;
                d = stb + (uint32_t)(ARR_A + r * (PSTR * 2) + s * 16);
            }
            CP16(d, g);
        }
        asm volatile("cp.async.commit_group;");
    };

    uint32_t aoff = (uint32_t)((warpM + (lane & 15)) * (PSTR * 2) + (lane >> 4) * 16);
    uint32_t boff = (uint32_t)(ARR_A +
                    (warpN + ((lane >> 4) << 3) + (lane & 7)) * (PSTR * 2) +
                    ((lane >> 3) & 1) * 16);

    auto ldfrag = [&](uint32_t stage, int kk, uint32_t (*Af)[4], uint32_t (*Bf)[2]) {
#pragma unroll
        for (int mt = 0; mt < 4; mt++) {
            uint32_t ad = stage + aoff + mt * (16 * PSTR * 2) + kk * 32;
            LDSM_X4(Af[mt][0], Af[mt][1], Af[mt][2], Af[mt][3], ad);
        }
#pragma unroll
        for (int np = 0; np < 4; np++) {
            uint32_t bd = stage + boff + np * (16 * PSTR * 2) + kk * 32;
            LDSM_X4(Bf[2*np][0], Bf[2*np][1], Bf[2*np+1][0], Bf[2*np+1][1], bd);
        }
    };

    uint32_t ah[2][4][4], bh8[2][8][2];

    const int nch = KDIM / 64;
    issue(0);
    issue(1);
    for (int c = 0; c < nch; c++) {
        if (c + 1 < nch) asm volatile("cp.async.wait_group 1;");
        else             asm volatile("cp.async.wait_group 0;");
        __syncthreads();
        if (c + 2 < nch) issue(c + 2);

        uint32_t stage = sbase + (uint32_t)((c % NSTAGE) * STAGE_B);
        ldfrag(stage, 0, ah[0], bh8[0]);
#pragma unroll
        for (int kk = 0; kk < 4; kk++) {
            int cur = kk & 1;
            if (kk < 3) ldfrag(stage, kk + 1, ah[cur ^ 1], bh8[cur ^ 1]);
#pragma unroll
            for (int mt = 0; mt < 4; mt++)
#pragma unroll
                for (int nt = 0; nt < 8; nt++)
                    MMA16816(acc[mt][nt], ah[cur][mt], bh8[cur][nt]);
        }
    }

    int row0 = blockIdx.y * 128 + warpM + (lane >> 2);
    int col0 = (bx & 1) * 256 + warpN + (lane & 3) * 2;
#pragma unroll
    for (int mt = 0; mt < 4; mt++) {
#pragma unroll
        for (int nt = 0; nt < 8; nt++) {
            int r = row0 + mt * 16;
            int cc = col0 + nt * 8;
            float b0 = bias[cc], b1 = bias[cc + 1];
            float2 d0, d1;
            d0.x = acc[mt][nt][0] + b0; d0.y = acc[mt][nt][1] + b1;
            d1.x = acc[mt][nt][2] + b0; d1.y = acc[mt][nt][3] + b1;
            if (HOUT) {
                d0.x = fmaxf(d0.x, 0.f); d0.y = fmaxf(d0.y, 0.f);
                d1.x = fmaxf(d1.x, 0.f); d1.y = fmaxf(d1.y, 0.f);
                __half* Ch = (__half*)C;
                *(__half2*)(Ch + (size_t)r * 512 + cc)       = __floats2half2_rn(d0.x, d0.y);
                *(__half2*)(Ch + (size_t)(r + 8) * 512 + cc) = __floats2half2_rn(d1.x, d1.y);
            } else {
                float* Cf = (float*)C;
                *(float2*)(Cf + (size_t)r * 512 + cc)       = d0;
                *(float2*)(Cf + (size_t)(r + 8) * 512 + cc) = d1;
            }
        }
    }
}

// ---------------------------------------------------------------------------
// Tensor-core causal attention with causal tile-skipping (unchanged from R9).
// ---------------------------------------------------------------------------
#define ATT_ROWB 144
#define ATT_ARR  (128 * ATT_ROWB)
#define ATT_SMEM (3 * ATT_ARR)

__global__ void __launch_bounds__(256)
attn_tc_kernel(const int* __restrict__ kpm,
               const __half* __restrict__ Q, const __half* __restrict__ Kp,
               const __half* __restrict__ V, __half* __restrict__ outp) {
    extern __shared__ char sm[];
    uint32_t sb = smem_u32(sm);

    int bid = blockIdx.x;
    int h = bid & 7;
    int n = (bid >> 3) % N_;
    int b = bid / (H_ * N_);
    int tid = threadIdx.x, wq = tid >> 5, lane = tid & 31;
    int L = kpm[b];
    int RN = ((L + 15) >> 4) << 4;
    if (RN > 128) RN = 128;

    size_t base = ((size_t)(b * T_) * N_ + n) * D_ + h * DH;
    const size_t rstride = (size_t)N_ * D_;

#pragma unroll
    for (int j = 0; j < 12; j++) {
        int idx = tid + j * 256;
        int arr = idx >> 10, rem = idx & 1023;
        int r = rem >> 3, s = rem & 7;
        if (arr == 0 || r < RN) {
            const __half* src = ((arr == 0) ? Q : (arr == 1) ? Kp : V)
                                + base + (size_t)r * rstride + s * 8;
            *(uint4*)(sm + arr * ATT_ARR + r * ATT_ROWB + s * 16) = *(const uint4*)src;
        }
    }
    __syncthreads();

    int kmax = min(wq, (L - 1) >> 4);

    uint32_t qa[4][4];
#pragma unroll
    for (int kt = 0; kt < 4; kt++) {
        uint32_t ad = sb + (wq * 16 + (lane & 15)) * ATT_ROWB
                         + (kt * 16 + (lane >> 4) * 8) * 2;
        LDSM_X4(qa[kt][0], qa[kt][1], qa[kt][2], qa[kt][3], ad);
    }

    float sa[16][4];
#pragma unroll
    for (int nt2 = 0; nt2 < 8; nt2++) {
        if (nt2 > kmax) continue;
        sa[2*nt2][0] = sa[2*nt2][1] = sa[2*nt2][2] = sa[2*nt2][3] = 0.f;
        sa[2*nt2+1][0] = sa[2*nt2+1][1] = sa[2*nt2+1][2] = sa[2*nt2+1][3] = 0.f;
#pragma unroll
        for (int kt = 0; kt < 4; kt++) {
            uint32_t bk0[2], bk1[2];
            uint32_t bd = sb + ATT_ARR
                        + (nt2 * 16 + ((lane >> 4) << 3) + (lane & 7)) * ATT_ROWB
                        + (kt * 16 + ((lane >> 3) & 1) * 8) * 2;
            LDSM_X4(bk0[0], bk0[1], bk1[0], bk1[1], bd);
            MMA16816(sa[2 * nt2],     qa[kt], bk0);
            MMA16816(sa[2 * nt2 + 1], qa[kt], bk1);
        }
    }

    const float NEGINF = -CUDART_INF_F;
    int r0 = wq * 16 + (lane >> 2);
    int r1 = r0 + 8;
    int c2 = (lane & 3) * 2;
    float m0 = NEGINF, m1 = NEGINF;
#pragma unroll
    for (int nt = 0; nt < 16; nt++) {
        if ((nt >> 1) > kmax) continue;
        int c0 = nt * 8 + c2;
#pragma unroll
        for (int e = 0; e < 4; e++) {
            int col = c0 + (e & 1);
            int row = (e < 2) ? r0 : r1;
            float s = sa[nt][e] * 0.125f;
            if (col > row || col >= L) s = NEGINF;
            sa[nt][e] = s;
            if (e < 2) m0 = fmaxf(m0, s); else m1 = fmaxf(m1, s);
        }
    }
    m0 = fmaxf(m0, __shfl_xor_sync(0xffffffffu, m0, 1));
    m0 = fmaxf(m0, __shfl_xor_sync(0xffffffffu, m0, 2));
    m1 = fmaxf(m1, __shfl_xor_sync(0xffffffffu, m1, 1));
    m1 = fmaxf(m1, __shfl_xor_sync(0xffffffffu, m1, 2));

    float l0 = 0.f, l1 = 0.f;
#pragma unroll
    for (int nt = 0; nt < 16; nt++) {
        if ((nt >> 1) > kmax) continue;
#pragma unroll
        for (int e = 0; e < 4; e++) {
            float p = __expf(sa[nt][e] - ((e < 2) ? m0 : m1));
            sa[nt][e] = p;
            if (e < 2) l0 += p; else l1 += p;
        }
    }
    l0 += __shfl_xor_sync(0xffffffffu, l0, 1);
    l0 += __shfl_xor_sync(0xffffffffu, l0, 2);
    l1 += __shfl_xor_sync(0xffffffffu, l1, 1);
    l1 += __shfl_xor_sync(0xffffffffu, l1, 2);

    float oa[8][4];
#pragma unroll
    for (int dt = 0; dt < 8; dt++)
#pragma unroll
        for (int e = 0; e < 4; e++) oa[dt][e] = 0.f;

#pragma unroll
    for (int kt = 0; kt < 8; kt++) {
        if (kt > kmax) continue;
        uint32_t pa[4];
        pa[0] = packh2(sa[2 * kt][0],     sa[2 * kt][1]);
        pa[1] = packh2(sa[2 * kt][2],     sa[2 * kt][3]);
        pa[2] = packh2(sa[2 * kt + 1][0], sa[2 * kt + 1][1]);
        pa[3] = packh2(sa[2 * kt + 1][2], sa[2 * kt + 1][3]);
#pragma unroll
        for (int dt2 = 0; dt2 < 4; dt2++) {
            uint32_t bv0[2], bv1[2];
            uint32_t bd = sb + 2 * ATT_ARR
                        + (kt * 16 + ((lane >> 3) & 1) * 8 + (lane & 7)) * ATT_ROWB
                        + (dt2 * 16 + ((lane >> 4) << 3)) * 2;
            LDSM_X4_T(bv0[0], bv0[1], bv1[0], bv1[1], bd);
            MMA16816(oa[2 * dt2],     pa, bv0);
            MMA16816(oa[2 * dt2 + 1], pa, bv1);
        }
    }

    float inv0 = 1.f / l0, inv1 = 1.f / l1;
    __half* op0 = outp + base + (size_t)r0 * rstride;
    __half* op1 = outp + base + (size_t)r1 * rstride;
#pragma unroll
    for (int dt = 0; dt < 8; dt++) {
        int c = dt * 8 + c2;
        *(__half2*)(op0 + c) = __floats2half2_rn(oa[dt][0] * inv0, oa[dt][1] * inv0);
        *(__half2*)(op1 + c) = __floats2half2_rn(oa[dt][2] * inv1, oa[dt][3] * inv1);
    }
}

// ---------------------------------------------------------------------------
extern "C" void kernel_launch(void* const* d_in, const int* in_sizes, int n_in,
                              void* d_out, int out_size) {
    const float* X   = (const float*)d_in[0];
    const float* TLE = (const float*)d_in[1];
    const int*   kpm = (const int*)  d_in[2];
    const float* Wq  = (const float*)d_in[3];
    const float* bq  = (const float*)d_in[4];
    const float* Wk  = (const float*)d_in[5];
    const float* bk  = (const float*)d_in[6];
    const float* Wv  = (const float*)d_in[7];
    const float* bv  = (const float*)d_in[8];
    const float* W1  = (const float*)d_in[9];
    const float* b1  = (const float*)d_in[10];
    const float* W2  = (const float*)d_in[11];
    const float* b2  = (const float*)d_in[12];
    float* out = (float*)d_out;

    __half *pAct, *pWh, *pq, *pk, *pv;
    cudaGetSymbolAddress((void**)&pAct, g_Act);
    cudaGetSymbolAddress((void**)&pWh, g_Wh);
    cudaGetSymbolAddress((void**)&pq, g_q);
    cudaGetSymbolAddress((void**)&pk, g_k);
    cudaGetSymbolAddress((void**)&pv, g_v);

    __half* actR0 = pAct;                       // attn out / W1 input
    __half* actR1 = pAct + (size_t)TOK * D_;    // FFN mid

    cudaFuncSetAttribute((const void*)qkv_gemm_fused,
                         cudaFuncAttributeMaxDynamicSharedMemorySize, QF_SMEM);
    cudaFuncSetAttribute((const void*)mma_gemm<1>,
                         cudaFuncAttributeMaxDynamicSharedMemorySize, SMEM_B);
    cudaFuncSetAttribute((const void*)mma_gemm<0>,
                         cudaFuncAttributeMaxDynamicSharedMemorySize, SMEM_B);
    cudaFuncSetAttribute((const void*)attn_tc_kernel,
                         cudaFuncAttributeMaxDynamicSharedMemorySize, ATT_SMEM);

    // 1. transpose all weights -> fp16 (single launch)
    wtrans_all_kernel<<<2883584 / 256, 256>>>(Wq, Wk, Wv, W1, W2);

    // 2. fused conv_H + QKV projection
    qkv_gemm_fused<<<dim3(6, TOK / 128), 256, QF_SMEM>>>(
        X, TLE, pWh, bq, bk, bv, pq, pk, pv);

    // 3. tensor-core causal attention -> fp16 region0
    attn_tc_kernel<<<B_ * N_ * H_, 256, ATT_SMEM>>>(kpm, pq, pk, pv, actR0);

    // 4. FFN
    mma_gemm<1><<<dim3(2, TOK / 128), 256, SMEM_B>>>(actR0, pWh + WOFF1, b1, actR1);
    mma_gemm<0><<<dim3(2, TOK / 128), 256, SMEM_B>>>(actR1, pWh + WOFF2, b2, out);
}

// round 11
// speedup vs baseline: 1.1065x; 1.1046x over previous
#include <cuda_runtime.h>
#include <cuda_fp16.h>
#include <math_constants.h>
#include <cstdint>

// Problem constants
#define B_   16
#define T_   128
#define N_   50
#define D_   512
#define H_   8
#define DH   64
#define TOK  (B_ * T_ * N_)      // 102400 tokens
#define K3   (3 * D_)            // 1536

// ---------------------------------------------------------------------------
// Scratch (device globals: allocation-free per harness rules)
// ---------------------------------------------------------------------------
__device__ __half g_Act[(size_t)TOK * K3];   // H for QKV; later attn out / FFN mid
__device__ __half g_q[(size_t)TOK * D_];
__device__ __half g_k[(size_t)TOK * D_];
__device__ __half g_v[(size_t)TOK * D_];
// Transposed fp16 weights: [Wq;Wk;Wv] stacked (1536 rows x K=1536), then W1, W2.
#define WOFF1 2359296
#define WOFF2 2621440
__device__ __half g_Wh[2883584];

// ---------------------------------------------------------------------------
// helpers
// ---------------------------------------------------------------------------
__device__ __forceinline__ uint32_t smem_u32(const void* p) {
    uint32_t a;
    asm("{ .reg .u64 t; cvta.to.shared.u64 t, %1; cvt.u32.u64 %0, t; }"
        : "=r"(a) : "l"(p));
    return a;
}

#define LDSM_X4(r0, r1, r2, r3, addr)                                         \
    asm volatile("ldmatrix.sync.aligned.m8n8.x4.shared.b16 {%0,%1,%2,%3}, [%4];" \
                 : "=r"(r0), "=r"(r1), "=r"(r2), "=r"(r3) : "r"(addr))

#define LDSM_X4_T(r0, r1, r2, r3, addr)                                       \
    asm volatile("ldmatrix.sync.aligned.m8n8.x4.trans.shared.b16 {%0,%1,%2,%3}, [%4];" \
                 : "=r"(r0), "=r"(r1), "=r"(r2), "=r"(r3) : "r"(addr))

#define MMA16816(d, a, b)                                                     \
    asm volatile("mma.sync.aligned.m16n8k16.row.col.f32.f16.f16.f32 "         \
                 "{%0,%1,%2,%3}, {%4,%5,%6,%7}, {%8,%9}, {%0,%1,%2,%3};"      \
                 : "+f"((d)[0]), "+f"((d)[1]), "+f"((d)[2]), "+f"((d)[3])     \
                 : "r"((a)[0]), "r"((a)[1]), "r"((a)[2]), "r"((a)[3]),        \
                   "r"((b)[0]), "r"((b)[1]))

#define CP16(dst, src)                                                        \
    asm volatile("cp.async.cg.shared.global [%0], [%1], 16;"                  \
                 :: "r"(dst), "l"(src))

__device__ __forceinline__ uint32_t packh2(float x, float y) {
    __half2 h = __floats2half2_rn(x, y);
    return *(uint32_t*)&h;
}

// ---------------------------------------------------------------------------
// All weight transposes in one launch.
// ---------------------------------------------------------------------------
__global__ void wtrans_all_kernel(const float* __restrict__ Wq,
                                  const float* __restrict__ Wk,
                                  const float* __restrict__ Wv,
                                  const float* __restrict__ W1,
                                  const float* __restrict__ W2) {
    int idx = blockIdx.x * 256 + threadIdx.x;
    const float* src;
    float v;
    if (idx < WOFF1) {
        int sel = idx / 786432, i = idx - sel * 786432;
        int n = i / K3, k = i - n * K3;
        src = (sel == 0) ? Wq : (sel == 1) ? Wk : Wv;
        v = src[(size_t)k * 512 + n];
    } else {
        int j = idx - WOFF1;
        int sel = j >> 18, i = j & 262143;
        int n = i >> 9, k = i & 511;
        src = sel ? W2 : W1;
        v = src[(size_t)k * 512 + n];
    }
    g_Wh[idx] = __float2half_rn(v);
}

// ---------------------------------------------------------------------------
// H = concat(X, TLE) -> fp16, 8 elems/thread  (R8-proven)
// ---------------------------------------------------------------------------
__global__ void conv_H_kernel(const float* __restrict__ X,
                              const float* __restrict__ TLE) {
    size_t i = ((size_t)blockIdx.x * 256 + threadIdx.x) * 8;
    size_t tok = i / K3;
    int c = (int)(i % K3);
    const float* src = (c < D_) ? (X + tok * D_ + c)
                                : (TLE + tok * (size_t)(2 * D_) + (c - D_));
    float4 a = *(const float4*)src;
    float4 b = *(const float4*)(src + 4);
    float f[8] = {a.x, a.y, a.z, a.w, b.x, b.y, b.z, b.w};
    __half h[8];
#pragma unroll
    for (int j = 0; j < 8; j++) h[j] = __float2half_rn(f[j]);
    *(uint4*)(g_Act + i) = *(uint4*)h;
}

// ---------------------------------------------------------------------------
// Tensor-core GEMM (R8-proven): C[*,512] = act(A @ Wt^T + bias)
//   CTA 128x256, 8 warps (2x4), warp tile 64x64, BK=64, 3-stage cp.async,
//   register double-buffered fragments, one barrier per K-chunk.
//   QKV fusion via blockIdx.x: reg = bx>>1 selects (bias_r, C_r).
// ---------------------------------------------------------------------------
#define PSTR     72
#define ARR_A    (128 * PSTR * 2)
#define ARR_Bt   (256 * PSTR * 2)
#define STAGE_B  (ARR_A + ARR_Bt)
#define NSTAGE   3
#define SMEM_B   (NSTAGE * STAGE_B)

template<int ACT, int HOUT, int KDIM>
__global__ void __launch_bounds__(256)
mma_gemm(const __half* __restrict__ A, const __half* __restrict__ Bh,
         const float* __restrict__ bias0, const float* __restrict__ bias1,
         const float* __restrict__ bias2,
         void* C0, void* C1, void* C2) {
    extern __shared__ char sm[];
    uint32_t sbase = smem_u32(sm);

    int tid = threadIdx.x, wid = tid >> 5, lane = tid & 31;
    int bx = blockIdx.x;
    int warpM = (wid >> 2) * 64;
    int warpN = (wid & 3) * 64;

    const __half* srcA = A  + (size_t)blockIdx.y * 128 * KDIM;
    const __half* srcB = Bh + (size_t)bx * 256 * KDIM;

    float acc[4][8][4];
#pragma unroll
    for (int i = 0; i < 4; i++)
#pragma unroll
        for (int j = 0; j < 8; j++)
#pragma unroll
            for (int e = 0; e < 4; e++) acc[i][j][e] = 0.f;

    auto issue = [&](int c) {
        uint32_t stb = sbase + (uint32_t)((c % NSTAGE) * STAGE_B);
        int k0 = c * 64;
#pragma unroll
        for (int j = 0; j < 12; j++) {
            int idx = tid + j * 256;
            const __half* g;
            uint32_t d;
            if (idx < 1024) {
                int r = idx >> 3, s = idx & 7;
                g = srcA + (size_t)r * KDIM + k0 + s * 8;
                d = stb + (uint32_t)(r * (PSTR * 2) + s * 16);
            } else {
                int r = (idx - 1024) >> 3, s = idx & 7;
                g = srcB + (size_t)r * KDIM + k0 + s * 8;
                d = stb + (uint32_t)(ARR_A + r * (PSTR * 2) + s * 16);
            }
            CP16(d, g);
        }
        asm volatile("cp.async.commit_group;");
    };

    uint32_t aoff = (uint32_t)((warpM + (lane & 15)) * (PSTR * 2) + (lane >> 4) * 16);
    uint32_t boff = (uint32_t)(ARR_A +
                    (warpN + ((lane >> 4) << 3) + (lane & 7)) * (PSTR * 2) +
                    ((lane >> 3) & 1) * 16);

    auto ldfrag = [&](uint32_t stage, int kk, uint32_t (*Af)[4], uint32_t (*Bf)[2]) {
#pragma unroll
        for (int mt = 0; mt < 4; mt++) {
            uint32_t ad = stage + aoff + mt * (16 * PSTR * 2) + kk * 32;
            LDSM_X4(Af[mt][0], Af[mt][1], Af[mt][2], Af[mt][3], ad);
        }
#pragma unroll
        for (int np = 0; np < 4; np++) {
            uint32_t bd = stage + boff + np * (16 * PSTR * 2) + kk * 32;
            LDSM_X4(Bf[2*np][0], Bf[2*np][1], Bf[2*np+1][0], Bf[2*np+1][1], bd);
        }
    };

    uint32_t ah[2][4][4], bh8[2][8][2];

    const int nch = KDIM / 64;
    issue(0);
    issue(1);
    for (int c = 0; c < nch; c++) {
        if (c + 1 < nch) asm volatile("cp.async.wait_group 1;");
        else             asm volatile("cp.async.wait_group 0;");
        __syncthreads();
        if (c + 2 < nch) issue(c + 2);

        uint32_t stage = sbase + (uint32_t)((c % NSTAGE) * STAGE_B);
        ldfrag(stage, 0, ah[0], bh8[0]);
#pragma unroll
        for (int kk = 0; kk < 4; kk++) {
            int cur = kk & 1;
            if (kk < 3) ldfrag(stage, kk + 1, ah[cur ^ 1], bh8[cur ^ 1]);
#pragma unroll
            for (int mt = 0; mt < 4; mt++)
#pragma unroll
                for (int nt = 0; nt < 8; nt++)
                    MMA16816(acc[mt][nt], ah[cur][mt], bh8[cur][nt]);
        }
    }

    int reg = bx >> 1;
    const float* bias = (reg == 0) ? bias0 : (reg == 1) ? bias1 : bias2;
    void* Cp          = (reg == 0) ? C0    : (reg == 1) ? C1    : C2;
    int row0 = blockIdx.y * 128 + warpM + (lane >> 2);
    int col0 = (bx & 1) * 256 + warpN + (lane & 3) * 2;
#pragma unroll
    for (int mt = 0; mt < 4; mt++) {
#pragma unroll
        for (int nt = 0; nt < 8; nt++) {
            int r = row0 + mt * 16;
            int cc = col0 + nt * 8;
            float b0 = bias[cc], b1 = bias[cc + 1];
            float2 d0, d1;
            d0.x = acc[mt][nt][0] + b0; d0.y = acc[mt][nt][1] + b1;
            d1.x = acc[mt][nt][2] + b0; d1.y = acc[mt][nt][3] + b1;
            if (ACT) {
                d0.x = fmaxf(d0.x, 0.f); d0.y = fmaxf(d0.y, 0.f);
                d1.x = fmaxf(d1.x, 0.f); d1.y = fmaxf(d1.y, 0.f);
            }
            if (HOUT) {
                __half* Ch = (__half*)Cp;
                *(__half2*)(Ch + (size_t)r * 512 + cc)       = __floats2half2_rn(d0.x, d0.y);
                *(__half2*)(Ch + (size_t)(r + 8) * 512 + cc) = __floats2half2_rn(d1.x, d1.y);
            } else {
                float* Cf = (float*)Cp;
                *(float2*)(Cf + (size_t)r * 512 + cc)       = d0;
                *(float2*)(Cf + (size_t)(r + 8) * 512 + cc) = d1;
            }
        }
    }
}

// ---------------------------------------------------------------------------
// Tensor-core causal attention with causal tile-skipping.
// 2 CTAs/SM via launch bounds (regs capped at 128; ~5 spills tolerable).
// ---------------------------------------------------------------------------
#define ATT_ROWB 144
#define ATT_ARR  (128 * ATT_ROWB)
#define ATT_SMEM (3 * ATT_ARR)

__global__ void __launch_bounds__(256, 2)
attn_tc_kernel(const int* __restrict__ kpm,
               const __half* __restrict__ Q, const __half* __restrict__ Kp,
               const __half* __restrict__ V, __half* __restrict__ outp) {
    extern __shared__ char sm[];
    uint32_t sb = smem_u32(sm);

    int bid = blockIdx.x;
    int h = bid & 7;
    int n = (bid >> 3) % N_;
    int b = bid / (H_ * N_);
    int tid = threadIdx.x, wq = tid >> 5, lane = tid & 31;
    int L = kpm[b];
    int RN = ((L + 15) >> 4) << 4;
    if (RN > 128) RN = 128;

    size_t base = ((size_t)(b * T_) * N_ + n) * D_ + h * DH;
    const size_t rstride = (size_t)N_ * D_;

#pragma unroll
    for (int j = 0; j < 12; j++) {
        int idx = tid + j * 256;
        int arr = idx >> 10, rem = idx & 1023;
        int r = rem >> 3, s = rem & 7;
        if (arr == 0 || r < RN) {
            const __half* src = ((arr == 0) ? Q : (arr == 1) ? Kp : V)
                                + base + (size_t)r * rstride + s * 8;
            *(uint4*)(sm + arr * ATT_ARR + r * ATT_ROWB + s * 16) = *(const uint4*)src;
        }
    }
    __syncthreads();

    int kmax = min(wq, (L - 1) >> 4);

    uint32_t qa[4][4];
#pragma unroll
    for (int kt = 0; kt < 4; kt++) {
        uint32_t ad = sb + (wq * 16 + (lane & 15)) * ATT_ROWB
                         + (kt * 16 + (lane >> 4) * 8) * 2;
        LDSM_X4(qa[kt][0], qa[kt][1], qa[kt][2], qa[kt][3], ad);
    }

    float sa[16][4];
#pragma unroll
    for (int nt2 = 0; nt2 < 8; nt2++) {
        if (nt2 > kmax) continue;
        sa[2*nt2][0] = sa[2*nt2][1] = sa[2*nt2][2] = sa[2*nt2][3] = 0.f;
        sa[2*nt2+1][0] = sa[2*nt2+1][1] = sa[2*nt2+1][2] = sa[2*nt2+1][3] = 0.f;
#pragma unroll
        for (int kt = 0; kt < 4; kt++) {
            uint32_t bk0[2], bk1[2];
            uint32_t bd = sb + ATT_ARR
                        + (nt2 * 16 + ((lane >> 4) << 3) + (lane & 7)) * ATT_ROWB
                        + (kt * 16 + ((lane >> 3) & 1) * 8) * 2;
            LDSM_X4(bk0[0], bk0[1], bk1[0], bk1[1], bd);
            MMA16816(sa[2 * nt2],     qa[kt], bk0);
            MMA16816(sa[2 * nt2 + 1], qa[kt], bk1);
        }
    }

    const float NEGINF = -CUDART_INF_F;
    int r0 = wq * 16 + (lane >> 2);
    int r1 = r0 + 8;
    int c2 = (lane & 3) * 2;
    float m0 = NEGINF, m1 = NEGINF;
#pragma unroll
    for (int nt = 0; nt < 16; nt++) {
        if ((nt >> 1) > kmax) continue;
        int c0 = nt * 8 + c2;
#pragma unroll
        for (int e = 0; e < 4; e++) {
            int col = c0 + (e & 1);
            int row = (e < 2) ? r0 : r1;
            float s = sa[nt][e] * 0.125f;
            if (col > row || col >= L) s = NEGINF;
            sa[nt][e] = s;
            if (e < 2) m0 = fmaxf(m0, s); else m1 = fmaxf(m1, s);
        }
    }
    m0 = fmaxf(m0, __shfl_xor_sync(0xffffffffu, m0, 1));
    m0 = fmaxf(m0, __shfl_xor_sync(0xffffffffu, m0, 2));
    m1 = fmaxf(m1, __shfl_xor_sync(0xffffffffu, m1, 1));
    m1 = fmaxf(m1, __shfl_xor_sync(0xffffffffu, m1, 2));

    float l0 = 0.f, l1 = 0.f;
#pragma unroll
    for (int nt = 0; nt < 16; nt++) {
        if ((nt >> 1) > kmax) continue;
#pragma unroll
        for (int e = 0; e < 4; e++) {
            float p = __expf(sa[nt][e] - ((e < 2) ? m0 : m1));
            sa[nt][e] = p;
            if (e < 2) l0 += p; else l1 += p;
        }
    }
    l0 += __shfl_xor_sync(0xffffffffu, l0, 1);
    l0 += __shfl_xor_sync(0xffffffffu, l0, 2);
    l1 += __shfl_xor_sync(0xffffffffu, l1, 1);
    l1 += __shfl_xor_sync(0xffffffffu, l1, 2);

    float oa[8][4];
#pragma unroll
    for (int dt = 0; dt < 8; dt++)
#pragma unroll
        for (int e = 0; e < 4; e++) oa[dt][e] = 0.f;

#pragma unroll
    for (int kt = 0; kt < 8; kt++) {
        if (kt > kmax) continue;
        uint32_t pa[4];
        pa[0] = packh2(sa[2 * kt][0],     sa[2 * kt][1]);
        pa[1] = packh2(sa[2 * kt][2],     sa[2 * kt][3]);
        pa[2] = packh2(sa[2 * kt + 1][0], sa[2 * kt + 1][1]);
        pa[3] = packh2(sa[2 * kt + 1][2], sa[2 * kt + 1][3]);
#pragma unroll
        for (int dt2 = 0; dt2 < 4; dt2++) {
            uint32_t bv0[2], bv1[2];
            uint32_t bd = sb + 2 * ATT_ARR
                        + (kt * 16 + ((lane >> 3) & 1) * 8 + (lane & 7)) * ATT_ROWB
                        + (dt2 * 16 + ((lane >> 4) << 3)) * 2;
            LDSM_X4_T(bv0[0], bv0[1], bv1[0], bv1[1], bd);
            MMA16816(oa[2 * dt2],     pa, bv0);
            MMA16816(oa[2 * dt2 + 1], pa, bv1);
        }
    }

    float inv0 = 1.f / l0, inv1 = 1.f / l1;
    __half* op0 = outp + base + (size_t)r0 * rstride;
    __half* op1 = outp + base + (size_t)r1 * rstride;
#pragma unroll
    for (int dt = 0; dt < 8; dt++) {
        int c = dt * 8 + c2;
        *(__half2*)(op0 + c) = __floats2half2_rn(oa[dt][0] * inv0, oa[dt][1] * inv0);
        *(__half2*)(op1 + c) = __floats2half2_rn(oa[dt][2] * inv1, oa[dt][3] * inv1);
    }
}

// ---------------------------------------------------------------------------
extern "C" void kernel_launch(void* const* d_in, const int* in_sizes, int n_in,
                              void* d_out, int out_size) {
    const float* X   = (const float*)d_in[0];
    const float* TLE = (const float*)d_in[1];
    const int*   kpm = (const int*)  d_in[2];
    const float* Wq  = (const float*)d_in[3];
    const float* bq  = (const float*)d_in[4];
    const float* Wk  = (const float*)d_in[5];
    const float* bk  = (const float*)d_in[6];
    const float* Wv  = (const float*)d_in[7];
    const float* bv  = (const float*)d_in[8];
    const float* W1  = (const float*)d_in[9];
    const float* b1  = (const float*)d_in[10];
    const float* W2  = (const float*)d_in[11];
    const float* b2  = (const float*)d_in[12];
    float* out = (float*)d_out;

    __half *pAct, *pWh, *pq, *pk, *pv;
    cudaGetSymbolAddress((void**)&pAct, g_Act);
    cudaGetSymbolAddress((void**)&pWh, g_Wh);
    cudaGetSymbolAddress((void**)&pq, g_q);
    cudaGetSymbolAddress((void**)&pk, g_k);
    cudaGetSymbolAddress((void**)&pv, g_v);

    __half* actR0 = pAct;                       // attn out / W1 input
    __half* actR1 = pAct + (size_t)TOK * D_;    // FFN mid

    cudaFuncSetAttribute((const void*)mma_gemm<1,1,1536>,
                         cudaFuncAttributeMaxDynamicSharedMemorySize, SMEM_B);
    cudaFuncSetAttribute((const void*)mma_gemm<1,1,512>,
                         cudaFuncAttributeMaxDynamicSharedMemorySize, SMEM_B);
    cudaFuncSetAttribute((const void*)mma_gemm<0,0,512>,
                         cudaFuncAttributeMaxDynamicSharedMemorySize, SMEM_B);
    cudaFuncSetAttribute((const void*)attn_tc_kernel,
                         cudaFuncAttributeMaxDynamicSharedMemorySize, ATT_SMEM);

    // 1. transpose all weights -> fp16 (single launch)
    wtrans_all_kernel<<<2883584 / 256, 256>>>(Wq, Wk, Wv, W1, W2);

    // 2. H = [X, TLE] -> fp16
    conv_H_kernel<<<(size_t)TOK * K3 / 8 / 256, 256>>>(X, TLE);

    // 3. fused QKV projection (single launch, 6 x 256-wide column blocks)
    mma_gemm<1,1,1536><<<dim3(6, TOK / 128), 256, SMEM_B>>>(
        pAct, pWh, bq, bk, bv, pq, pk, pv);

    // 4. tensor-core causal attention -> fp16 region0
    attn_tc_kernel<<<B_ * N_ * H_, 256, ATT_SMEM>>>(kpm, pq, pk, pv, actR0);

    // 5. FFN
    mma_gemm<1,1,512><<<dim3(2, TOK / 128), 256, SMEM_B>>>(
        actR0, pWh + WOFF1, b1, b1, b1, actR1, actR1, actR1);
    mma_gemm<0,0,512><<<dim3(2, TOK / 128), 256, SMEM_B>>>(
        actR1, pWh + WOFF2, b2, b2, b2, out, out, out);
}

// round 13
// speedup vs baseline: 1.1182x; 1.0106x over previous
#include <cuda_runtime.h>
#include <cuda_fp16.h>
#include <math_constants.h>
#include <cstdint>

// Problem constants
#define B_   16
#define T_   128
#define N_   50
#define D_   512
#define H_   8
#define DH   64
#define TOK  (B_ * T_ * N_)      // 102400 tokens
#define K3   (3 * D_)            // 1536

// ---------------------------------------------------------------------------
// Scratch (device globals: allocation-free per harness rules)
// ---------------------------------------------------------------------------
__device__ __half g_Act[(size_t)TOK * K3];   // H for QKV; later attn out / FFN mid
__device__ __half g_q[(size_t)TOK * D_];
__device__ __half g_k[(size_t)TOK * D_];
__device__ __half g_v[(size_t)TOK * D_];
// Transposed fp16 weights: [Wq;Wk;Wv] stacked (1536 rows x K=1536), then W1, W2.
#define WOFF1 2359296
#define WOFF2 2621440
__device__ __half g_Wh[2883584];

// ---------------------------------------------------------------------------
// helpers
// ---------------------------------------------------------------------------
__device__ __forceinline__ uint32_t smem_u32(const void* p) {
    uint32_t a;
    asm("{ .reg .u64 t; cvta.to.shared.u64 t, %1; cvt.u32.u64 %0, t; }"
        : "=r"(a) : "l"(p));
    return a;
}

#define LDSM_X4(r0, r1, r2, r3, addr)                                         \
    asm volatile("ldmatrix.sync.aligned.m8n8.x4.shared.b16 {%0,%1,%2,%3}, [%4];" \
                 : "=r"(r0), "=r"(r1), "=r"(r2), "=r"(r3) : "r"(addr))

#define LDSM_X4_T(r0, r1, r2, r3, addr)                                       \
    asm volatile("ldmatrix.sync.aligned.m8n8.x4.trans.shared.b16 {%0,%1,%2,%3}, [%4];" \
                 : "=r"(r0), "=r"(r1), "=r"(r2), "=r"(r3) : "r"(addr))

#define MMA16816(d, a, b)                                                     \
    asm volatile("mma.sync.aligned.m16n8k16.row.col.f32.f16.f16.f32 "         \
                 "{%0,%1,%2,%3}, {%4,%5,%6,%7}, {%8,%9}, {%0,%1,%2,%3};"      \
                 : "+f"((d)[0]), "+f"((d)[1]), "+f"((d)[2]), "+f"((d)[3])     \
                 : "r"((a)[0]), "r"((a)[1]), "r"((a)[2]), "r"((a)[3]),        \
                   "r"((b)[0]), "r"((b)[1]))

#define CP16(dst, src)                                                        \
    asm volatile("cp.async.cg.shared.global [%0], [%1], 16;"                  \
                 :: "r"(dst), "l"(src))

__device__ __forceinline__ uint32_t packh2(float x, float y) {
    __half2 h = __floats2half2_rn(x, y);
    return *(uint32_t*)&h;
}

// ---------------------------------------------------------------------------
// All weight transposes in one launch.
// ---------------------------------------------------------------------------
__global__ void wtrans_all_kernel(const float* __restrict__ Wq,
                                  const float* __restrict__ Wk,
                                  const float* __restrict__ Wv,
                                  const float* __restrict__ W1,
                                  const float* __restrict__ W2) {
    int idx = blockIdx.x * 256 + threadIdx.x;
    const float* src;
    float v;
    if (idx < WOFF1) {
        int sel = idx / 786432, i = idx - sel * 786432;
        int n = i / K3, k = i - n * K3;
        src = (sel == 0) ? Wq : (sel == 1) ? Wk : Wv;
        v = src[(size_t)k * 512 + n];
    } else {
        int j = idx - WOFF1;
        int sel = j >> 18, i = j & 262143;
        int n = i >> 9, k = i & 511;
        src = sel ? W2 : W1;
        v = src[(size_t)k * 512 + n];
    }
    g_Wh[idx] = __float2half_rn(v);
}

// ---------------------------------------------------------------------------
// H = concat(X, TLE) -> fp16, 8 elems/thread
// ---------------------------------------------------------------------------
__global__ void conv_H_kernel(const float* __restrict__ X,
                              const float* __restrict__ TLE) {
    size_t i = ((size_t)blockIdx.x * 256 + threadIdx.x) * 8;
    size_t tok = i / K3;
    int c = (int)(i % K3);
    const float* src = (c < D_) ? (X + tok * D_ + c)
                                : (TLE + tok * (size_t)(2 * D_) + (c - D_));
    float4 a = *(const float4*)src;
    float4 b = *(const float4*)(src + 4);
    float f[8] = {a.x, a.y, a.z, a.w, b.x, b.y, b.z, b.w};
    __half h[8];
#pragma unroll
    for (int j = 0; j < 8; j++) h[j] = __float2half_rn(f[j]);
    *(uint4*)(g_Act + i) = *(uint4*)h;
}

// ---------------------------------------------------------------------------
// Tensor-core GEMM (R8-proven): C[*,512] = act(A @ Wt^T + bias)
// ---------------------------------------------------------------------------
#define PSTR     72
#define ARR_A    (128 * PSTR * 2)
#define ARR_Bt   (256 * PSTR * 2)
#define STAGE_B  (ARR_A + ARR_Bt)
#define NSTAGE   3
#define SMEM_B   (NSTAGE * STAGE_B)

template<int ACT, int HOUT, int KDIM>
__global__ void __launch_bounds__(256)
mma_gemm(const __half* __restrict__ A, const __half* __restrict__ Bh,
         const float* __restrict__ bias0, const float* __restrict__ bias1,
         const float* __restrict__ bias2,
         void* C0, void* C1, void* C2) {
    extern __shared__ char sm[];
    uint32_t sbase = smem_u32(sm);

    int tid = threadIdx.x, wid = tid >> 5, lane = tid & 31;
    int bx = blockIdx.x;
    int warpM = (wid >> 2) * 64;
    int warpN = (wid & 3) * 64;

    const __half* srcA = A  + (size_t)blockIdx.y * 128 * KDIM;
    const __half* srcB = Bh + (size_t)bx * 256 * KDIM;

    float acc[4][8][4];
#pragma unroll
    for (int i = 0; i < 4; i++)
#pragma unroll
        for (int j = 0; j < 8; j++)
#pragma unroll
            for (int e = 0; e < 4; e++) acc[i][j][e] = 0.f;

    auto issue = [&](int c) {
        uint32_t stb = sbase + (uint32_t)((c % NSTAGE) * STAGE_B);
        int k0 = c * 64;
#pragma unroll
        for (int j = 0; j < 12; j++) {
            int idx = tid + j * 256;
            const __half* g;
            uint32_t d;
            if (idx < 1024) {
                int r = idx >> 3, s = idx & 7;
                g = srcA + (size_t)r * KDIM + k0 + s * 8;
                d = stb + (uint32_t)(r * (PSTR * 2) + s * 16);
            } else {
                int r = (idx - 1024) >> 3, s = idx & 7;
                g = srcB + (size_t)r * KDIM + k0 + s * 8;
                d = stb + (uint32_t)(ARR_A + r * (PSTR * 2) + s * 16);
            }
            CP16(d, g);
        }
        asm volatile("cp.async.commit_group;");
    };

    uint32_t aoff = (uint32_t)((warpM + (lane & 15)) * (PSTR * 2) + (lane >> 4) * 16);
    uint32_t boff = (uint32_t)(ARR_A +
                    (warpN + ((lane >> 4) << 3) + (lane & 7)) * (PSTR * 2) +
                    ((lane >> 3) & 1) * 16);

    auto ldfrag = [&](uint32_t stage, int kk, uint32_t (*Af)[4], uint32_t (*Bf)[2]) {
#pragma unroll
        for (int mt = 0; mt < 4; mt++) {
            uint32_t ad = stage + aoff + mt * (16 * PSTR * 2) + kk * 32;
            LDSM_X4(Af[mt][0], Af[mt][1], Af[mt][2], Af[mt][3], ad);
        }
#pragma unroll
        for (int np = 0; np < 4; np++) {
            uint32_t bd = stage + boff + np * (16 * PSTR * 2) + kk * 32;
            LDSM_X4(Bf[2*np][0], Bf[2*np][1], Bf[2*np+1][0], Bf[2*np+1][1], bd);
        }
    };

    uint32_t ah[2][4][4], bh8[2][8][2];

    const int nch = KDIM / 64;
    issue(0);
    issue(1);
    for (int c = 0; c < nch; c++) {
        if (c + 1 < nch) asm volatile("cp.async.wait_group 1;");
        else             asm volatile("cp.async.wait_group 0;");
        __syncthreads();
        if (c + 2 < nch) issue(c + 2);

        uint32_t stage = sbase + (uint32_t)((c % NSTAGE) * STAGE_B);
        ldfrag(stage, 0, ah[0], bh8[0]);
#pragma unroll
        for (int kk = 0; kk < 4; kk++) {
            int cur = kk & 1;
            if (kk < 3) ldfrag(stage, kk + 1, ah[cur ^ 1], bh8[cur ^ 1]);
#pragma unroll
            for (int mt = 0; mt < 4; mt++)
#pragma unroll
                for (int nt = 0; nt < 8; nt++)
                    MMA16816(acc[mt][nt], ah[cur][mt], bh8[cur][nt]);
        }
    }

    int reg = bx >> 1;
    const float* bias = (reg == 0) ? bias0 : (reg == 1) ? bias1 : bias2;
    void* Cp          = (reg == 0) ? C0    : (reg == 1) ? C1    : C2;
    int row0 = blockIdx.y * 128 + warpM + (lane >> 2);
    int col0 = (bx & 1) * 256 + warpN + (lane & 3) * 2;
#pragma unroll
    for (int mt = 0; mt < 4; mt++) {
#pragma unroll
        for (int nt = 0; nt < 8; nt++) {
            int r = row0 + mt * 16;
            int cc = col0 + nt * 8;
            float b0 = bias[cc], b1 = bias[cc + 1];
            float2 d0, d1;
            d0.x = acc[mt][nt][0] + b0; d0.y = acc[mt][nt][1] + b1;
            d1.x = acc[mt][nt][2] + b0; d1.y = acc[mt][nt][3] + b1;
            if (ACT) {
                d0.x = fmaxf(d0.x, 0.f); d0.y = fmaxf(d0.y, 0.f);
                d1.x = fmaxf(d1.x, 0.f); d1.y = fmaxf(d1.y, 0.f);
            }
            if (HOUT) {
                __half* Ch = (__half*)Cp;
                *(__half2*)(Ch + (size_t)r * 512 + cc)       = __floats2half2_rn(d0.x, d0.y);
                *(__half2*)(Ch + (size_t)(r + 8) * 512 + cc) = __floats2half2_rn(d1.x, d1.y);
            } else {
                float* Cf = (float*)Cp;
                *(float2*)(Cf + (size_t)r * 512 + cc)       = d0;
                *(float2*)(Cf + (size_t)(r + 8) * 512 + cc) = d1;
            }
        }
    }
}

// ---------------------------------------------------------------------------
// Tensor-core causal attention, two-tile pipelined.
// grid = 3200; each CTA processes tiles bid and bid+3200. Both tiles'
// Q/K/V staged via cp.async into separate buffers up-front, so tile-1's
// DRAM fetch overlaps tile-0's compute. Compute math identical to R11.
// ---------------------------------------------------------------------------
#define ATT_ROWB 144
#define ATT_ARR  (128 * ATT_ROWB)      // 18432
#define ATT_BUF  (3 * ATT_ARR)         // 55296 per tile
#define ATT_SMEM (2 * ATT_BUF)         // 110592

__global__ void __launch_bounds__(256, 2)
attn_tc_kernel(const int* __restrict__ kpm,
               const __half* __restrict__ Q, const __half* __restrict__ Kp,
               const __half* __restrict__ V, __half* __restrict__ outp) {
    extern __shared__ char sm[];
    uint32_t sb = smem_u32(sm);

    int tid = threadIdx.x, wq = tid >> 5, lane = tid & 31;
    const size_t rstride = (size_t)N_ * D_;

    int    Ls[2];
    int    RNs[2];
    size_t bases[2];
#pragma unroll
    for (int t = 0; t < 2; t++) {
        int bid = blockIdx.x + t * 3200;
        int h = bid & 7;
        int n = (bid >> 3) % N_;
        int b = bid / (H_ * N_);
        Ls[t] = kpm[b];
        int RN = ((Ls[t] + 15) >> 4) << 4;
        RNs[t] = (RN > 128) ? 128 : RN;
        bases[t] = ((size_t)(b * T_) * N_ + n) * D_ + h * DH;
    }

    // issue staging for both tiles (one commit group each)
#pragma unroll
    for (int t = 0; t < 2; t++) {
        uint32_t dstb = sb + t * ATT_BUF;
        size_t base = bases[t];
        int RN = RNs[t];
#pragma unroll
        for (int j = 0; j < 12; j++) {
            int idx = tid + j * 256;
            int arr = idx >> 10, rem = idx & 1023;
            int r = rem >> 3, s = rem & 7;
            if (arr == 0 || r < RN) {
                const __half* src = ((arr == 0) ? Q : (arr == 1) ? Kp : V)
                                    + base + (size_t)r * rstride + s * 8;
                CP16(dstb + (uint32_t)(arr * ATT_ARR + r * ATT_ROWB + s * 16), src);
            }
        }
        asm volatile("cp.async.commit_group;");
    }

#pragma unroll
    for (int t = 0; t < 2; t++) {
        if (t == 0) asm volatile("cp.async.wait_group 1;");
        else        asm volatile("cp.async.wait_group 0;");
        __syncthreads();

        uint32_t sbt = sb + t * ATT_BUF;
        int L = Ls[t];
        size_t base = bases[t];
        int kmax = min(wq, (L - 1) >> 4);

        uint32_t qa[4][4];
#pragma unroll
        for (int kt = 0; kt < 4; kt++) {
            uint32_t ad = sbt + (wq * 16 + (lane & 15)) * ATT_ROWB
                              + (kt * 16 + (lane >> 4) * 8) * 2;
            LDSM_X4(qa[kt][0], qa[kt][1], qa[kt][2], qa[kt][3], ad);
        }

        float sa[16][4];
#pragma unroll
        for (int nt2 = 0; nt2 < 8; nt2++) {
            if (nt2 > kmax) continue;
            sa[2*nt2][0] = sa[2*nt2][1] = sa[2*nt2][2] = sa[2*nt2][3] = 0.f;
            sa[2*nt2+1][0] = sa[2*nt2+1][1] = sa[2*nt2+1][2] = sa[2*nt2+1][3] = 0.f;
#pragma unroll
            for (int kt = 0; kt < 4; kt++) {
                uint32_t bk0[2], bk1[2];
                uint32_t bd = sbt + ATT_ARR
                            + (nt2 * 16 + ((lane >> 4) << 3) + (lane & 7)) * ATT_ROWB
                            + (kt * 16 + ((lane >> 3) & 1) * 8) * 2;
                LDSM_X4(bk0[0], bk0[1], bk1[0], bk1[1], bd);
                MMA16816(sa[2 * nt2],     qa[kt], bk0);
                MMA16816(sa[2 * nt2 + 1], qa[kt], bk1);
            }
        }

        const float NEGINF = -CUDART_INF_F;
        int r0 = wq * 16 + (lane >> 2);
        int r1 = r0 + 8;
        int c2 = (lane & 3) * 2;
        float m0 = NEGINF, m1 = NEGINF;
#pragma unroll
        for (int nt = 0; nt < 16; nt++) {
            if ((nt >> 1) > kmax) continue;
            int c0 = nt * 8 + c2;
#pragma unroll
            for (int e = 0; e < 4; e++) {
                int col = c0 + (e & 1);
                int row = (e < 2) ? r0 : r1;
                float s = sa[nt][e] * 0.125f;
                if (col > row || col >= L) s = NEGINF;
                sa[nt][e] = s;
                if (e < 2) m0 = fmaxf(m0, s); else m1 = fmaxf(m1, s);
            }
        }
        m0 = fmaxf(m0, __shfl_xor_sync(0xffffffffu, m0, 1));
        m0 = fmaxf(m0, __shfl_xor_sync(0xffffffffu, m0, 2));
        m1 = fmaxf(m1, __shfl_xor_sync(0xffffffffu, m1, 1));
        m1 = fmaxf(m1, __shfl_xor_sync(0xffffffffu, m1, 2));

        float l0 = 0.f, l1 = 0.f;
#pragma unroll
        for (int nt = 0; nt < 16; nt++) {
            if ((nt >> 1) > kmax) continue;
#pragma unroll
            for (int e = 0; e < 4; e++) {
                float p = __expf(sa[nt][e] - ((e < 2) ? m0 : m1));
                sa[nt][e] = p;
                if (e < 2) l0 += p; else l1 += p;
            }
        }
        l0 += __shfl_xor_sync(0xffffffffu, l0, 1);
        l0 += __shfl_xor_sync(0xffffffffu, l0, 2);
        l1 += __shfl_xor_sync(0xffffffffu, l1, 1);
        l1 += __shfl_xor_sync(0xffffffffu, l1, 2);

        float oa[8][4];
#pragma unroll
        for (int dt = 0; dt < 8; dt++)
#pragma unroll
            for (int e = 0; e < 4; e++) oa[dt][e] = 0.f;

#pragma unroll
        for (int kt = 0; kt < 8; kt++) {
            if (kt > kmax) continue;
            uint32_t pa[4];
            pa[0] = packh2(sa[2 * kt][0],     sa[2 * kt][1]);
            pa[1] = packh2(sa[2 * kt][2],     sa[2 * kt][3]);
            pa[2] = packh2(sa[2 * kt + 1][0], sa[2 * kt + 1][1]);
            pa[3] = packh2(sa[2 * kt + 1][2], sa[2 * kt + 1][3]);
#pragma unroll
            for (int dt2 = 0; dt2 < 4; dt2++) {
                uint32_t bv0[2], bv1[2];
                uint32_t bd = sbt + 2 * ATT_ARR
                            + (kt * 16 + ((lane >> 3) & 1) * 8 + (lane & 7)) * ATT_ROWB
                            + (dt2 * 16 + ((lane >> 4) << 3)) * 2;
                LDSM_X4_T(bv0[0], bv0[1], bv1[0], bv1[1], bd);
                MMA16816(oa[2 * dt2],     pa, bv0);
                MMA16816(oa[2 * dt2 + 1], pa, bv1);
            }
        }

        float inv0 = 1.f / l0, inv1 = 1.f / l1;
        __half* op0 = outp + base + (size_t)r0 * rstride;
        __half* op1 = outp + base + (size_t)r1 * rstride;
#pragma unroll
        for (int dt = 0; dt < 8; dt++) {
            int c = dt * 8 + c2;
            *(__half2*)(op0 + c) = __floats2half2_rn(oa[dt][0] * inv0, oa[dt][1] * inv0);
            *(__half2*)(op1 + c) = __floats2half2_rn(oa[dt][2] * inv1, oa[dt][3] * inv1);
        }
    }
}

// ---------------------------------------------------------------------------
extern "C" void kernel_launch(void* const* d_in, const int* in_sizes, int n_in,
                              void* d_out, int out_size) {
    const float* X   = (const float*)d_in[0];
    const float* TLE = (const float*)d_in[1];
    const int*   kpm = (const int*)  d_in[2];
    const float* Wq  = (const float*)d_in[3];
    const float* bq  = (const float*)d_in[4];
    const float* Wk  = (const float*)d_in[5];
    const float* bk  = (const float*)d_in[6];
    const float* Wv  = (const float*)d_in[7];
    const float* bv  = (const float*)d_in[8];
    const float* W1  = (const float*)d_in[9];
    const float* b1  = (const float*)d_in[10];
    const float* W2  = (const float*)d_in[11];
    const float* b2  = (const float*)d_in[12];
    float* out = (float*)d_out;

    __half *pAct, *pWh, *pq, *pk, *pv;
    cudaGetSymbolAddress((void**)&pAct, g_Act);
    cudaGetSymbolAddress((void**)&pWh, g_Wh);
    cudaGetSymbolAddress((void**)&pq, g_q);
    cudaGetSymbolAddress((void**)&pk, g_k);
    cudaGetSymbolAddress((void**)&pv, g_v);

    __half* actR0 = pAct;                       // attn out / W1 input
    __half* actR1 = pAct + (size_t)TOK * D_;    // FFN mid

    cudaFuncSetAttribute((const void*)mma_gemm<1,1,1536>,
                         cudaFuncAttributeMaxDynamicSharedMemorySize, SMEM_B);
    cudaFuncSetAttribute((const void*)mma_gemm<1,1,512>,
                         cudaFuncAttributeMaxDynamicSharedMemorySize, SMEM_B);
    cudaFuncSetAttribute((const void*)mma_gemm<0,0,512>,
                         cudaFuncAttributeMaxDynamicSharedMemorySize, SMEM_B);
    cudaFuncSetAttribute((const void*)attn_tc_kernel,
                         cudaFuncAttributeMaxDynamicSharedMemorySize, ATT_SMEM);

    // 1. transpose all weights -> fp16 (single launch)
    wtrans_all_kernel<<<2883584 / 256, 256>>>(Wq, Wk, Wv, W1, W2);

    // 2. H = [X, TLE] -> fp16
    conv_H_kernel<<<(size_t)TOK * K3 / 8 / 256, 256>>>(X, TLE);

    // 3. fused QKV projection (single launch, 6 x 256-wide column blocks)
    mma_gemm<1,1,1536><<<dim3(6, TOK / 128), 256, SMEM_B>>>(
        pAct, pWh, bq, bk, bv, pq, pk, pv);

    // 4. tensor-core causal attention, two tiles per CTA -> fp16 region0
    attn_tc_kernel<<<B_ * N_ * H_ / 2, 256, ATT_SMEM>>>(kpm, pq, pk, pv, actR0);

    // 5. FFN
    mma_gemm<1,1,512><<<dim3(2, TOK / 128), 256, SMEM_B>>>(
        actR0, pWh + WOFF1, b1, b1, b1, actR1, actR1, actR1);
    mma_gemm<0,0,512><<<dim3(2, TOK / 128), 256, SMEM_B>>>(
        actR1, pWh + WOFF2, b2, b2, b2, out, out, out);
}